// round 15
// baseline (speedup 1.0000x reference)
#include <cuda_runtime.h>
#include <cuda_fp16.h>
#include <cstdint>

// ---------------------------------------------------------------------------
// LocalSensitiveAttention on GB300 (sm_103 baseline ptx: legacy HMMA mma.sync)
// Round 15: R13 split pipeline (prep converts values->fp16 at DRAM roofline;
// main is pure cp.async) + KC=128 in main (5 barriers instead of 9).
// Pure fp16 x fp16 GEMM, fp32 accum. Tile 128a x 128t, warp 32a x 64t.
// ---------------------------------------------------------------------------

#define B_    64
#define T_    2048
#define DEC_  1024
#define ENC_  512
#define ATT_  128
#define LOC_  32
#define KW_   31

__device__ float g_q[B_ * ATT_];
__device__ float g_energies[B_ * T_];
__device__ float g_ctx_part[B_ * 16 * ENC_];
__device__ __align__(16) uint32_t g_Ahi[ATT_ * 256];  // Vw fp16 pairs [a][256]
__device__ __align__(16) uint32_t g_Lhi[ATT_ * 16];   // Weff (pad k32) [a][16]
// fp16 image of values: written by prep, read by main_mma (cp.async) and ctx
__device__ __align__(16) __half2 g_vh[(size_t)B_ * T_ * ENC_ / 2];

#define CVT_BLKS 32768   // (B*T*ENC/8) uint4 conversions / 256 threads

// ----------------------------- helpers -------------------------------------
__device__ __forceinline__ uint32_t smem_u32(const void* p) {
    uint32_t a;
    asm("{ .reg .u64 t; cvta.to.shared.u64 t, %1; cvt.u32.u64 %0, t; }"
        : "=r"(a) : "l"(p));
    return a;
}
#define CP_ASYNC16(dst, src) \
    asm volatile("cp.async.cg.shared.global [%0], [%1], 16;" :: "r"(dst), "l"(src))
#define CP_COMMIT() asm volatile("cp.async.commit_group;" ::: "memory")
#define CP_WAIT0()  asm volatile("cp.async.wait_group 0;" ::: "memory")

__device__ __forceinline__ void ldsm4(uint32_t* r, uint32_t addr) {
    asm volatile("ldmatrix.sync.aligned.m8n8.x4.shared.b16 {%0,%1,%2,%3}, [%4];"
                 : "=r"(r[0]), "=r"(r[1]), "=r"(r[2]), "=r"(r[3]) : "r"(addr));
}
__device__ __forceinline__ void hmma(float* c, const uint32_t* a,
                                     const uint32_t* b) {
    asm volatile(
        "mma.sync.aligned.m16n8k16.row.col.f32.f16.f16.f32 "
        "{%0,%1,%2,%3},{%4,%5,%6,%7},{%8,%9},{%0,%1,%2,%3};"
        : "+f"(c[0]), "+f"(c[1]), "+f"(c[2]), "+f"(c[3])
        : "r"(a[0]), "r"(a[1]), "r"(a[2]), "r"(a[3]), "r"(b[0]), "r"(b[1]));
}
__device__ __forceinline__ uint32_t pack_h2(float a, float b) {
    __half2 h = __floats2half2_rn(a, b);
    return *reinterpret_cast<uint32_t*>(&h);
}
__device__ __forceinline__ float tanh_acc(float x) {
    x = fminf(fmaxf(x, -15.f), 15.f);
    float t, r;
    asm("ex2.approx.f32 %0, %1;" : "=f"(t) : "f"(x * 2.8853900817779268f));
    asm("rcp.approx.f32 %0, %1;" : "=f"(r) : "f"(t + 1.f));
    return (t - 1.f) * r;
}

// ---------------------------------------------------------------------------
// fused prep: 0..63 q; 64..191 pack_A; 192..199 pack_L; 200.. values->fp16
// ---------------------------------------------------------------------------
__global__ void prep_kernel(const float* __restrict__ query,
                            const float* __restrict__ Qw,
                            const float* __restrict__ Qb,
                            const float* __restrict__ Vw,
                            const float* __restrict__ lp,
                            const float* __restrict__ cw,
                            const float* __restrict__ values) {
    int bid = blockIdx.x, tid = threadIdx.x;
    if (bid >= 200) {                    // values -> g_vh (fp16), streaming
        size_t u = (size_t)(bid - 200) * 256 + tid;  // uint4 id
        const float4* src = (const float4*)values;
        float4 a = src[2 * u], b2 = src[2 * u + 1];
        uint4 p;
        p.x = pack_h2(a.x, a.y);
        p.y = pack_h2(a.z, a.w);
        p.z = pack_h2(b2.x, b2.y);
        p.w = pack_h2(b2.z, b2.w);
        ((uint4*)g_vh)[u] = p;
    } else if (bid < 64) {               // q = query @ Qw^T + Qb
        int b = bid, wid = tid >> 5, lane = tid & 31;
        #pragma unroll 1
        for (int ai = 0; ai < 16; ai++) {
            int a = wid * 16 + ai;
            float s = 0.f;
            #pragma unroll 8
            for (int k = lane; k < DEC_; k += 32)
                s += query[b * DEC_ + k] * Qw[a * DEC_ + k];
            #pragma unroll
            for (int o = 16; o > 0; o >>= 1)
                s += __shfl_down_sync(0xffffffffu, s, o);
            if (lane == 0) g_q[b * ATT_ + a] = s + Qb[a];
        }
    } else if (bid < 192) {              // pack Vw -> fp16
        int a = bid - 64;
        g_Ahi[a * 256 + tid] =
            pack_h2(Vw[a * ENC_ + 2 * tid], Vw[a * ENC_ + 2 * tid + 1]);
    } else {                             // Weff + pack
        int idx = (bid - 192) * 256 + tid;   // 0..2047 = 128*16
        int a = idx >> 4, p = idx & 15;
        int k0 = 2 * p, k1 = k0 + 1;
        float w0 = 0.f, w1 = 0.f;
        #pragma unroll
        for (int c = 0; c < LOC_; c++) {
            float l = lp[a * LOC_ + c];
            w0 += l * cw[c * KW_ + k0];
            if (k1 < KW_) w1 += l * cw[c * KW_ + k1];
        }
        g_Lhi[idx] = pack_h2(w0, w1);
    }
}

// ---------------------------------------------------------------------------
// main energies kernel: 256 threads, tile 128a x 128t, warp tile 32a x 64t
// 4 chunks of k=128 + 1 loc chunk of k=32; A + B pure cp.async, dbl buffered
// ---------------------------------------------------------------------------
#define NT     256
#define LDR    272       // smem row stride bytes (128 fp16 = 256B + 16B pad)
#define A_TILE 34816     // 128 rows * 272B
#define B_TILE 34816     // 128 t-rows * 272B
#define OFF_A   0                        // 2 buf x A_TILE = 69632
#define OFF_B   69632                    // 2 buf x B_TILE = 69632
#define OFF_CAW 139264                   // 160 floats
#define OFF_Q   139904                   // 128 floats
#define OFF_VWV 140416                   // 128 floats
#define OFF_RED 140928                   // 512 floats = 2048 B
#define SMEM_MAIN (OFF_RED + 2048)       // 142976 B -> 1 CTA/SM

// KC=128 chunk A loader (c in 0..3): 8 cp.async/thread
__device__ __forceinline__ void load_A_async128(uint32_t dstbase, int c, int tid) {
    #pragma unroll
    for (int i = 0; i < 8; i++) {
        int idx = tid + i * NT;           // 0..2047
        int row = idx >> 4, seg = idx & 15;
        const uint32_t* src = g_Ahi + row * 256 + c * 64 + seg * 4;
        uint32_t dst = dstbase + row * LDR + seg * 16;
        CP_ASYNC16(dst, src);
    }
}
// loc chunk (k=32) A loader: 2 cp.async/thread
__device__ __forceinline__ void load_A_asyncL(uint32_t dstbase, int tid) {
    #pragma unroll
    for (int i = 0; i < 2; i++) {
        int idx = tid + i * NT;           // 0..511
        int row = idx >> 2, seg = idx & 3;
        const uint32_t* src = g_Lhi + row * 16 + seg * 4;
        uint32_t dst = dstbase + row * LDR + seg * 16;
        CP_ASYNC16(dst, src);
    }
}
// KC=128 B loader from g_vh: 8 cp.async/thread (16B = 4 half2)
__device__ __forceinline__ void load_B_async128(uint32_t dstbase, int c, int tid,
                                                const __half2* __restrict__ vhb) {
    #pragma unroll
    for (int i = 0; i < 8; i++) {
        int idx = tid + i * NT;           // 0..2047
        int row = idx >> 4, seg = idx & 15;
        const __half2* src = vhb + (size_t)row * 256 + c * 64 + seg * 4;
        uint32_t dst = dstbase + row * LDR + seg * 16;
        CP_ASYNC16(dst, src);
    }
}
// loc chunk B: caw band from smem
__device__ __forceinline__ void load_B_regsL(const float* __restrict__ caw_s,
                                             int tid, float4* v) {
    #pragma unroll
    for (int j = 0; j < 4; j++) {
        int idx = tid + j * NT;           // 0..1023
        int row = idx >> 3, col4 = idx & 7;
        int k0 = col4 * 4;
        v[j].x = (k0 + 0 < KW_) ? caw_s[row + k0 + 0] : 0.f;
        v[j].y = (k0 + 1 < KW_) ? caw_s[row + k0 + 1] : 0.f;
        v[j].z = (k0 + 2 < KW_) ? caw_s[row + k0 + 2] : 0.f;
        v[j].w = (k0 + 3 < KW_) ? caw_s[row + k0 + 3] : 0.f;
    }
}
__device__ __forceinline__ void store_BL(char* smem, uint32_t bufoff, int tid,
                                         const float4* v) {
    #pragma unroll
    for (int j = 0; j < 4; j++) {
        int idx = tid + j * NT;
        int row = idx >> 3, col4 = idx & 7;
        uint32_t p01 = pack_h2(v[j].x, v[j].y);
        uint32_t p23 = pack_h2(v[j].z, v[j].w);
        *(uint2*)(smem + OFF_B + bufoff + row * LDR + col4 * 8) =
            make_uint2(p01, p23);
    }
}

template <int NK16>
__device__ __forceinline__ void compute_chunk(float (&acc)[2][8][4], uint32_t sb,
                                              int buf, int wm, int wn, int lane) {
    const uint32_t smA = sb + OFF_A + buf * A_TILE;
    const uint32_t smB = sb + OFF_B + buf * B_TILE;
    #pragma unroll
    for (int k16 = 0; k16 < NK16; k16++) {
        const int colb = k16 * 32;
        uint32_t ahi[2][4];
        #pragma unroll
        for (int mt = 0; mt < 2; mt++) {
            uint32_t ad = smA + (wm + mt * 16 + (lane & 15)) * LDR + colb +
                          ((lane >> 4) << 4);
            ldsm4(ahi[mt], ad);
        }
        uint32_t bfr[4][4];
        #pragma unroll
        for (int np = 0; np < 4; np++) {
            int grp = lane >> 3;
            uint32_t bd = smB + (wn + np * 16 + (grp >> 1) * 8 + (lane & 7)) * LDR +
                          colb + ((grp & 1) << 4);
            ldsm4(bfr[np], bd);
        }
        #pragma unroll
        for (int mt = 0; mt < 2; mt++)
            #pragma unroll
            for (int nt = 0; nt < 8; nt++) {
                const uint32_t* bp = &bfr[nt >> 1][(nt & 1) * 2];
                hmma(acc[mt][nt], ahi[mt], bp);
            }
    }
}

__global__ __launch_bounds__(NT, 1)
void main_mma(const float* __restrict__ caw,
              const float* __restrict__ vw_vec) {
    extern __shared__ __align__(16) char smem[];
    const uint32_t sb = smem_u32(smem);
    const int tid = threadIdx.x, wid = tid >> 5, lane = tid & 31;
    const int b = blockIdx.y, t0 = blockIdx.x * 128;
    const int wm = (wid & 3) * 32, wn = (wid >> 2) * 64;

    float* caw_s = (float*)(smem + OFF_CAW);
    float* q_s   = (float*)(smem + OFF_Q);
    float* vwv_s = (float*)(smem + OFF_VWV);
    float* red_s = (float*)(smem + OFF_RED);

    if (tid < 158) {
        int gt = t0 - 15 + tid;
        caw_s[tid] = (gt >= 0 && gt < T_) ? caw[b * T_ + gt] : 0.f;
    }
    if (tid >= 128 && tid < 256) {       // second half loads q/vwv
        int a = tid - 128;
        q_s[a]   = g_q[b * ATT_ + a];
        vwv_s[a] = vw_vec[a];
    }
    __syncthreads();

    const __half2* vhb = g_vh + (size_t)(b * T_ + t0) * (ENC_ / 2);
    float acc[2][8][4];
    #pragma unroll
    for (int i = 0; i < 2; i++)
        #pragma unroll
        for (int j = 0; j < 8; j++)
            #pragma unroll
            for (int e = 0; e < 4; e++) acc[i][j][e] = 0.f;

    // prologue: chunk 0 (A + B all async)
    load_A_async128(sb + OFF_A, 0, tid);
    load_B_async128(sb + OFF_B, 0, tid, vhb);
    CP_COMMIT();
    CP_WAIT0();
    __syncthreads();

    float4 v[4];
    #pragma unroll 1
    for (int c = 0; c < 4; c++) {
        const int nb = c + 1;
        const uint32_t nAo = (nb & 1) * A_TILE;
        const uint32_t nBo = (nb & 1) * B_TILE;
        if (nb < 4) {
            load_A_async128(sb + OFF_A + nAo, nb, tid);
            load_B_async128(sb + OFF_B + nBo, nb, tid, vhb);
            CP_COMMIT();
        } else {
            load_A_asyncL(sb + OFF_A + nAo, tid);   // loc -> buf 0 (4&1==0)
            CP_COMMIT();
            load_B_regsL(caw_s, tid, v);
        }
        compute_chunk<8>(acc, sb, c & 1, wm, wn, lane);
        if (nb == 4) store_BL(smem, nBo, tid, v);   // caw band -> buf 0
        CP_WAIT0();
        __syncthreads();
    }
    compute_chunk<2>(acc, sb, 0, wm, wn, lane);     // loc chunk, buf 0

    // epilogue: tanh + weighted reduce over a
    float part[8][2];
    #pragma unroll
    for (int nt = 0; nt < 8; nt++) { part[nt][0] = 0.f; part[nt][1] = 0.f; }
    const int r0 = lane >> 2;
    #pragma unroll
    for (int mt = 0; mt < 2; mt++) {
        #pragma unroll
        for (int half = 0; half < 2; half++) {
            int a = wm + mt * 16 + r0 + half * 8;
            float qa = q_s[a], va = vwv_s[a];
            #pragma unroll
            for (int nt = 0; nt < 8; nt++) {
                #pragma unroll
                for (int p = 0; p < 2; p++) {
                    float x = acc[mt][nt][half * 2 + p] + qa;
                    part[nt][p] += va * tanh_acc(x);
                }
            }
        }
    }
    #pragma unroll
    for (int off = 4; off < 32; off <<= 1)
        #pragma unroll
        for (int nt = 0; nt < 8; nt++) {
            part[nt][0] += __shfl_xor_sync(0xffffffffu, part[nt][0], off);
            part[nt][1] += __shfl_xor_sync(0xffffffffu, part[nt][1], off);
        }
    if (lane < 4) {
        #pragma unroll
        for (int nt = 0; nt < 8; nt++) {
            red_s[(wid & 3) * 128 + wn + nt * 8 + lane * 2 + 0] = part[nt][0];
            red_s[(wid & 3) * 128 + wn + nt * 8 + lane * 2 + 1] = part[nt][1];
        }
    }
    __syncthreads();
    if (tid < 128)
        g_energies[b * T_ + t0 + tid] = (red_s[tid] + red_s[128 + tid]) +
                                        (red_s[256 + tid] + red_s[384 + tid]);
}

// ---------------------------------------------------------------------------
// masked softmax over T per b
// ---------------------------------------------------------------------------
__global__ void softmax_kernel(const unsigned char* __restrict__ maskb,
                               float* __restrict__ out_w) {
    __shared__ float red[256];
    int b = blockIdx.x, tid = threadIdx.x;
    float e[8];
    float mx = -3.402823466e38f;
    #pragma unroll
    for (int i = 0; i < 8; i++) {
        int t = tid + i * 256;
        float v = g_energies[b * T_ + t];
        if (maskb[b * T_ + t]) v = __int_as_float(0xff800000);
        e[i] = v;
        mx = fmaxf(mx, v);
    }
    red[tid] = mx;
    __syncthreads();
    for (int s = 128; s > 0; s >>= 1) {
        if (tid < s) red[tid] = fmaxf(red[tid], red[tid + s]);
        __syncthreads();
    }
    mx = red[0];
    __syncthreads();
    float sum = 0.f;
    #pragma unroll
    for (int i = 0; i < 8; i++) {
        e[i] = expf(e[i] - mx);
        sum += e[i];
    }
    red[tid] = sum;
    __syncthreads();
    for (int s = 128; s > 0; s >>= 1) {
        if (tid < s) red[tid] += red[tid + s];
        __syncthreads();
    }
    float inv = 1.f / red[0];
    #pragma unroll
    for (int i = 0; i < 8; i++)
        out_w[b * T_ + tid + i * 256] = e[i] * inv;
}

// ---------------------------------------------------------------------------
// context = weights @ values(fp16 image): uint4 loads of 8 halves per thread
// ---------------------------------------------------------------------------
__global__ void ctx_partial(const float* __restrict__ w) {
    __shared__ float sw[128];
    __shared__ float sh[3][64][8];
    int b = blockIdx.y, ch = blockIdx.x, tid = threadIdx.x;  // 256 threads
    int col8 = tid & 63, parity = tid >> 6;                  // 0..3
    const __half2* vb = g_vh + (size_t)(b * T_ + ch * 128) * (ENC_ / 2);
    if (tid < 128) sw[tid] = w[b * T_ + ch * 128 + tid];
    __syncthreads();
    float acc[8];
    #pragma unroll
    for (int k = 0; k < 8; k++) acc[k] = 0.f;
    #pragma unroll 4
    for (int r = parity; r < 128; r += 4) {
        float wt = sw[r];
        uint4 raw = *(const uint4*)(vb + (size_t)r * (ENC_ / 2) + col8 * 4);
        const __half2* h = (const __half2*)&raw;
        #pragma unroll
        for (int k = 0; k < 4; k++) {
            float2 f = __half22float2(h[k]);
            acc[2 * k + 0] += wt * f.x;
            acc[2 * k + 1] += wt * f.y;
        }
    }
    if (parity > 0) {
        #pragma unroll
        for (int k = 0; k < 8; k++) sh[parity - 1][col8][k] = acc[k];
    }
    __syncthreads();
    if (parity == 0) {
        #pragma unroll
        for (int k = 0; k < 8; k++)
            acc[k] += sh[0][col8][k] + sh[1][col8][k] + sh[2][col8][k];
        float4* dst = (float4*)&g_ctx_part[(size_t)(b * 16 + ch) * ENC_ + col8 * 8];
        dst[0] = make_float4(acc[0], acc[1], acc[2], acc[3]);
        dst[1] = make_float4(acc[4], acc[5], acc[6], acc[7]);
    }
}

__global__ void ctx_reduce(float* __restrict__ out_ctx) {
    int idx = blockIdx.x * 256 + threadIdx.x;
    int b = idx >> 9, c = idx & 511;
    float s = 0.f;
    #pragma unroll
    for (int ch = 0; ch < 16; ch++)
        s += g_ctx_part[(size_t)(b * 16 + ch) * ENC_ + c];
    out_ctx[idx] = s;
}

// ---------------------------------------------------------------------------
extern "C" void kernel_launch(void* const* d_in, const int* in_sizes, int n_in,
                              void* d_out, int out_size) {
    const float* query = (const float*)d_in[0];
    const float* values = (const float*)d_in[1];
    const float* caw   = (const float*)d_in[2];
    const unsigned char* mask = (const unsigned char*)d_in[3];
    const float* Qw    = (const float*)d_in[4];
    const float* Qb    = (const float*)d_in[5];
    const float* Vw    = (const float*)d_in[6];
    const float* convw = (const float*)d_in[7];
    const float* locp  = (const float*)d_in[8];
    const float* vw    = (const float*)d_in[9];

    float* out_ctx = (float*)d_out;              // [B, ENC]
    float* out_w   = (float*)d_out + B_ * ENC_;  // [B, T]

    cudaFuncSetAttribute(main_mma,
                         cudaFuncAttributeMaxDynamicSharedMemorySize, SMEM_MAIN);

    prep_kernel<<<200 + CVT_BLKS, 256>>>(query, Qw, Qb, Vw, locp, convw, values);
    main_mma<<<dim3(T_ / 128, B_), NT, SMEM_MAIN>>>(caw, vw);
    softmax_kernel<<<B_, 256>>>(mask, out_w);
    ctx_partial<<<dim3(16, B_), 256>>>(out_w);
    ctx_reduce<<<(B_ * ENC_) / 256, 256>>>(out_ctx);
}

// round 16
// speedup vs baseline: 1.1299x; 1.1299x over previous
#include <cuda_runtime.h>
#include <cuda_fp16.h>
#include <cstdint>

// ---------------------------------------------------------------------------
// LocalSensitiveAttention on GB300 (sm_103 baseline ptx: legacy HMMA mma.sync)
// Round 16: R13 config (KC=64, 2 CTA/SM — established optimum) +
//  (1) softmax fused into ctx pass (deletes softmax kernel),
//  (2) conversion stage 2x ILP (2 uint4/thread).
// Pure fp16 x fp16 GEMM, fp32 accum; prep converts values->fp16 (g_vh).
// ---------------------------------------------------------------------------

#define B_    64
#define T_    2048
#define DEC_  1024
#define ENC_  512
#define ATT_  128
#define LOC_  32
#define KW_   31

__device__ float g_q[B_ * ATT_];
__device__ float g_energies[B_ * T_];
__device__ float g_ctx_part[B_ * 16 * ENC_];
__device__ __align__(16) uint32_t g_Ahi[ATT_ * 256];  // Vw fp16 pairs [a][256]
__device__ __align__(16) uint32_t g_Lhi[ATT_ * 16];   // Weff (pad k32) [a][16]
// fp16 image of values: written by prep, read by main_mma (cp.async) and ctx
__device__ __align__(16) __half2 g_vh[(size_t)B_ * T_ * ENC_ / 2];

#define CVT_BLKS 16384   // 8.39M uint4 / (256 threads * 2 per thread)

// ----------------------------- helpers -------------------------------------
__device__ __forceinline__ uint32_t smem_u32(const void* p) {
    uint32_t a;
    asm("{ .reg .u64 t; cvta.to.shared.u64 t, %1; cvt.u32.u64 %0, t; }"
        : "=r"(a) : "l"(p));
    return a;
}
#define CP_ASYNC16(dst, src) \
    asm volatile("cp.async.cg.shared.global [%0], [%1], 16;" :: "r"(dst), "l"(src))
#define CP_COMMIT() asm volatile("cp.async.commit_group;" ::: "memory")
#define CP_WAIT0()  asm volatile("cp.async.wait_group 0;" ::: "memory")

__device__ __forceinline__ void ldsm4(uint32_t* r, uint32_t addr) {
    asm volatile("ldmatrix.sync.aligned.m8n8.x4.shared.b16 {%0,%1,%2,%3}, [%4];"
                 : "=r"(r[0]), "=r"(r[1]), "=r"(r[2]), "=r"(r[3]) : "r"(addr));
}
__device__ __forceinline__ void hmma(float* c, const uint32_t* a,
                                     const uint32_t* b) {
    asm volatile(
        "mma.sync.aligned.m16n8k16.row.col.f32.f16.f16.f32 "
        "{%0,%1,%2,%3},{%4,%5,%6,%7},{%8,%9},{%0,%1,%2,%3};"
        : "+f"(c[0]), "+f"(c[1]), "+f"(c[2]), "+f"(c[3])
        : "r"(a[0]), "r"(a[1]), "r"(a[2]), "r"(a[3]), "r"(b[0]), "r"(b[1]));
}
__device__ __forceinline__ uint32_t pack_h2(float a, float b) {
    __half2 h = __floats2half2_rn(a, b);
    return *reinterpret_cast<uint32_t*>(&h);
}
__device__ __forceinline__ float tanh_acc(float x) {
    x = fminf(fmaxf(x, -15.f), 15.f);
    float t, r;
    asm("ex2.approx.f32 %0, %1;" : "=f"(t) : "f"(x * 2.8853900817779268f));
    asm("rcp.approx.f32 %0, %1;" : "=f"(r) : "f"(t + 1.f));
    return (t - 1.f) * r;
}

// ---------------------------------------------------------------------------
// fused prep: 0..63 q; 64..191 pack_A; 192..199 pack_L; 200.. values->fp16
// ---------------------------------------------------------------------------
__global__ void prep_kernel(const float* __restrict__ query,
                            const float* __restrict__ Qw,
                            const float* __restrict__ Qb,
                            const float* __restrict__ Vw,
                            const float* __restrict__ lp,
                            const float* __restrict__ cw,
                            const float* __restrict__ values) {
    int bid = blockIdx.x, tid = threadIdx.x;
    if (bid >= 200) {                    // values -> g_vh (fp16), 2 uint4/thr
        const float4* src = (const float4*)values;
        size_t base = (size_t)(bid - 200) * 512 + tid;
        #pragma unroll
        for (int k = 0; k < 2; k++) {
            size_t u = base + (size_t)k * 256;
            float4 a = src[2 * u], b2 = src[2 * u + 1];
            uint4 p;
            p.x = pack_h2(a.x, a.y);
            p.y = pack_h2(a.z, a.w);
            p.z = pack_h2(b2.x, b2.y);
            p.w = pack_h2(b2.z, b2.w);
            ((uint4*)g_vh)[u] = p;
        }
    } else if (bid < 64) {               // q = query @ Qw^T + Qb
        int b = bid, wid = tid >> 5, lane = tid & 31;
        #pragma unroll 1
        for (int ai = 0; ai < 16; ai++) {
            int a = wid * 16 + ai;
            float s = 0.f;
            #pragma unroll 8
            for (int k = lane; k < DEC_; k += 32)
                s += query[b * DEC_ + k] * Qw[a * DEC_ + k];
            #pragma unroll
            for (int o = 16; o > 0; o >>= 1)
                s += __shfl_down_sync(0xffffffffu, s, o);
            if (lane == 0) g_q[b * ATT_ + a] = s + Qb[a];
        }
    } else if (bid < 192) {              // pack Vw -> fp16
        int a = bid - 64;
        g_Ahi[a * 256 + tid] =
            pack_h2(Vw[a * ENC_ + 2 * tid], Vw[a * ENC_ + 2 * tid + 1]);
    } else {                             // Weff + pack
        int idx = (bid - 192) * 256 + tid;   // 0..2047 = 128*16
        int a = idx >> 4, p = idx & 15;
        int k0 = 2 * p, k1 = k0 + 1;
        float w0 = 0.f, w1 = 0.f;
        #pragma unroll
        for (int c = 0; c < LOC_; c++) {
            float l = lp[a * LOC_ + c];
            w0 += l * cw[c * KW_ + k0];
            if (k1 < KW_) w1 += l * cw[c * KW_ + k1];
        }
        g_Lhi[idx] = pack_h2(w0, w1);
    }
}

// ---------------------------------------------------------------------------
// main energies kernel: 256 threads, tile 128a x 128t, warp tile 32a x 64t
// 8 chunks of k=64 + 1 loc chunk of k=32; single fp16 A + B, dbl buffered
// ---------------------------------------------------------------------------
#define NT     256
#define LDR    144       // smem row stride bytes (64 fp16 = 128B data + 16B pad)
#define A_TILE 18432     // 128 rows * 144B
#define B_TILE 18432     // 128 t-rows * 144B
#define OFF_A   0                        // 2 buf x A_TILE = 36864
#define OFF_B   36864                    // 2 buf x B_TILE = 36864
#define OFF_CAW 73728                    // 160 floats
#define OFF_Q   74368                    // 128 floats
#define OFF_VWV 74880                    // 128 floats
#define OFF_RED 75392                    // 512 floats = 2048 B
#define SMEM_MAIN (OFF_RED + 2048)       // 77440 B -> 2 CTAs/SM

// KC=64 chunk A loader (c in 0..7): 4 cp.async/thread
__device__ __forceinline__ void load_A_async64(uint32_t dstbase, int c, int tid) {
    #pragma unroll
    for (int i = 0; i < 4; i++) {
        int idx = tid + i * NT;           // 0..1023
        int row = idx >> 3, seg = idx & 7;
        const uint32_t* src = g_Ahi + row * 256 + c * 32 + seg * 4;
        uint32_t dst = dstbase + row * LDR + seg * 16;
        CP_ASYNC16(dst, src);
    }
}
// loc chunk (k=32) A loader: 2 cp.async/thread
__device__ __forceinline__ void load_A_asyncL(uint32_t dstbase, int tid) {
    #pragma unroll
    for (int i = 0; i < 2; i++) {
        int idx = tid + i * NT;           // 0..511
        int row = idx >> 2, seg = idx & 3;
        const uint32_t* src = g_Lhi + row * 16 + seg * 4;
        uint32_t dst = dstbase + row * LDR + seg * 16;
        CP_ASYNC16(dst, src);
    }
}
// B loader: fp16 image from g_vh, 128 t-rows x 64 k, 4 cp.async/thread
__device__ __forceinline__ void load_B_async64(uint32_t dstbase, int c, int tid,
                                               const __half2* __restrict__ vhb) {
    #pragma unroll
    for (int i = 0; i < 4; i++) {
        int idx = tid + i * NT;           // 0..1023
        int row = idx >> 3, seg = idx & 7;
        const __half2* src = vhb + (size_t)row * 256 + c * 32 + seg * 4;
        uint32_t dst = dstbase + row * LDR + seg * 16;
        CP_ASYNC16(dst, src);
    }
}
// loc chunk B: caw band from smem
__device__ __forceinline__ void load_B_regsL(const float* __restrict__ caw_s,
                                             int tid, float4* v) {
    #pragma unroll
    for (int j = 0; j < 4; j++) {
        int idx = tid + j * NT;           // 0..1023
        int row = idx >> 3, col4 = idx & 7;
        int k0 = col4 * 4;
        v[j].x = (k0 + 0 < KW_) ? caw_s[row + k0 + 0] : 0.f;
        v[j].y = (k0 + 1 < KW_) ? caw_s[row + k0 + 1] : 0.f;
        v[j].z = (k0 + 2 < KW_) ? caw_s[row + k0 + 2] : 0.f;
        v[j].w = (k0 + 3 < KW_) ? caw_s[row + k0 + 3] : 0.f;
    }
}
__device__ __forceinline__ void store_BL(char* smem, uint32_t bufoff, int tid,
                                         const float4* v) {
    #pragma unroll
    for (int j = 0; j < 4; j++) {
        int idx = tid + j * NT;
        int row = idx >> 3, col4 = idx & 7;
        uint32_t p01 = pack_h2(v[j].x, v[j].y);
        uint32_t p23 = pack_h2(v[j].z, v[j].w);
        *(uint2*)(smem + OFF_B + bufoff + row * LDR + col4 * 8) =
            make_uint2(p01, p23);
    }
}

template <int NK16>
__device__ __forceinline__ void compute_chunk(float (&acc)[2][8][4], uint32_t sb,
                                              int buf, int wm, int wn, int lane) {
    const uint32_t smA = sb + OFF_A + buf * A_TILE;
    const uint32_t smB = sb + OFF_B + buf * B_TILE;
    #pragma unroll
    for (int k16 = 0; k16 < NK16; k16++) {
        const int colb = k16 * 32;
        uint32_t ahi[2][4];
        #pragma unroll
        for (int mt = 0; mt < 2; mt++) {
            uint32_t ad = smA + (wm + mt * 16 + (lane & 15)) * LDR + colb +
                          ((lane >> 4) << 4);
            ldsm4(ahi[mt], ad);
        }
        uint32_t bfr[4][4];
        #pragma unroll
        for (int np = 0; np < 4; np++) {
            int grp = lane >> 3;
            uint32_t bd = smB + (wn + np * 16 + (grp >> 1) * 8 + (lane & 7)) * LDR +
                          colb + ((grp & 1) << 4);
            ldsm4(bfr[np], bd);
        }
        #pragma unroll
        for (int mt = 0; mt < 2; mt++)
            #pragma unroll
            for (int nt = 0; nt < 8; nt++) {
                const uint32_t* bp = &bfr[nt >> 1][(nt & 1) * 2];
                hmma(acc[mt][nt], ahi[mt], bp);
            }
    }
}

__global__ __launch_bounds__(NT, 2)
void main_mma(const float* __restrict__ caw,
              const float* __restrict__ vw_vec) {
    extern __shared__ __align__(16) char smem[];
    const uint32_t sb = smem_u32(smem);
    const int tid = threadIdx.x, wid = tid >> 5, lane = tid & 31;
    const int b = blockIdx.y, t0 = blockIdx.x * 128;
    const int wm = (wid & 3) * 32, wn = (wid >> 2) * 64;

    float* caw_s = (float*)(smem + OFF_CAW);
    float* q_s   = (float*)(smem + OFF_Q);
    float* vwv_s = (float*)(smem + OFF_VWV);
    float* red_s = (float*)(smem + OFF_RED);

    if (tid < 158) {
        int gt = t0 - 15 + tid;
        caw_s[tid] = (gt >= 0 && gt < T_) ? caw[b * T_ + gt] : 0.f;
    }
    if (tid >= 128 && tid < 256) {       // second half loads q/vwv
        int a = tid - 128;
        q_s[a]   = g_q[b * ATT_ + a];
        vwv_s[a] = vw_vec[a];
    }
    __syncthreads();

    const __half2* vhb = g_vh + (size_t)(b * T_ + t0) * (ENC_ / 2);
    float acc[2][8][4];
    #pragma unroll
    for (int i = 0; i < 2; i++)
        #pragma unroll
        for (int j = 0; j < 8; j++)
            #pragma unroll
            for (int e = 0; e < 4; e++) acc[i][j][e] = 0.f;

    // prologue: chunk 0 (A + B all async)
    load_A_async64(sb + OFF_A, 0, tid);
    load_B_async64(sb + OFF_B, 0, tid, vhb);
    CP_COMMIT();
    CP_WAIT0();
    __syncthreads();

    float4 v[4];
    #pragma unroll 1
    for (int c = 0; c < 8; c++) {
        const int nb = c + 1;
        const uint32_t nAo = (nb & 1) * A_TILE;
        const uint32_t nBo = (nb & 1) * B_TILE;
        if (nb < 8) {
            load_A_async64(sb + OFF_A + nAo, nb, tid);
            load_B_async64(sb + OFF_B + nBo, nb, tid, vhb);
            CP_COMMIT();
        } else {
            load_A_asyncL(sb + OFF_A + nAo, tid);   // loc -> buf 0 (8&1==0)
            CP_COMMIT();
            load_B_regsL(caw_s, tid, v);
        }
        compute_chunk<4>(acc, sb, c & 1, wm, wn, lane);
        if (nb == 8) store_BL(smem, nBo, tid, v);   // caw band -> buf 0
        CP_WAIT0();
        __syncthreads();
    }
    compute_chunk<2>(acc, sb, 0, wm, wn, lane);     // loc chunk, buf 0

    // epilogue: tanh + weighted reduce over a
    float part[8][2];
    #pragma unroll
    for (int nt = 0; nt < 8; nt++) { part[nt][0] = 0.f; part[nt][1] = 0.f; }
    const int r0 = lane >> 2;
    #pragma unroll
    for (int mt = 0; mt < 2; mt++) {
        #pragma unroll
        for (int half = 0; half < 2; half++) {
            int a = wm + mt * 16 + r0 + half * 8;
            float qa = q_s[a], va = vwv_s[a];
            #pragma unroll
            for (int nt = 0; nt < 8; nt++) {
                #pragma unroll
                for (int p = 0; p < 2; p++) {
                    float x = acc[mt][nt][half * 2 + p] + qa;
                    part[nt][p] += va * tanh_acc(x);
                }
            }
        }
    }
    #pragma unroll
    for (int off = 4; off < 32; off <<= 1)
        #pragma unroll
        for (int nt = 0; nt < 8; nt++) {
            part[nt][0] += __shfl_xor_sync(0xffffffffu, part[nt][0], off);
            part[nt][1] += __shfl_xor_sync(0xffffffffu, part[nt][1], off);
        }
    if (lane < 4) {
        #pragma unroll
        for (int nt = 0; nt < 8; nt++) {
            red_s[(wid & 3) * 128 + wn + nt * 8 + lane * 2 + 0] = part[nt][0];
            red_s[(wid & 3) * 128 + wn + nt * 8 + lane * 2 + 1] = part[nt][1];
        }
    }
    __syncthreads();
    if (tid < 128)
        g_energies[b * T_ + t0 + tid] = (red_s[tid] + red_s[128 + tid]) +
                                        (red_s[256 + tid] + red_s[384 + tid]);
}

// ---------------------------------------------------------------------------
// ctx_fused: per-(b,ch) block recomputes masked softmax stats over full T,
// writes its 128 attention weights to out_w, and accumulates its context
// partial from the fp16 values image. Replaces softmax_kernel + ctx_partial.
// ---------------------------------------------------------------------------
__global__ void ctx_fused(const unsigned char* __restrict__ maskb,
                          float* __restrict__ out_w) {
    __shared__ float red[256];
    __shared__ float sw[128];
    __shared__ float sh[3][64][8];
    int b = blockIdx.y, ch = blockIdx.x, tid = threadIdx.x;  // 256 threads

    // masked softmax stats over full T (identical math to old softmax_kernel)
    float e[8];
    float mx = -3.402823466e38f;
    #pragma unroll
    for (int i = 0; i < 8; i++) {
        int t = tid + i * 256;
        float vv = g_energies[b * T_ + t];
        if (maskb[b * T_ + t]) vv = __int_as_float(0xff800000);
        e[i] = vv;
        mx = fmaxf(mx, vv);
    }
    red[tid] = mx;
    __syncthreads();
    for (int s = 128; s > 0; s >>= 1) {
        if (tid < s) red[tid] = fmaxf(red[tid], red[tid + s]);
        __syncthreads();
    }
    mx = red[0];
    __syncthreads();
    float sum = 0.f;
    #pragma unroll
    for (int i = 0; i < 8; i++) {
        e[i] = expf(e[i] - mx);
        sum += e[i];
    }
    red[tid] = sum;
    __syncthreads();
    for (int s = 128; s > 0; s >>= 1) {
        if (tid < s) red[tid] += red[tid + s];
        __syncthreads();
    }
    float inv = 1.f / red[0];
    __syncthreads();

    // this chunk's rows t = ch*128 + r live in e[ch>>1] of threads
    // tid in [ (ch&1)*128, (ch&1)*128+128 )
    {
        int i0 = ch >> 1, half = (ch & 1) * 128;
        if (tid >= half && tid < half + 128) {
            float wv = e[i0] * inv;
            sw[tid - half] = wv;
            out_w[b * T_ + ch * 128 + (tid - half)] = wv;
        }
    }
    __syncthreads();

    // context partial accumulation (fp16 image), as before
    int col8 = tid & 63, parity = tid >> 6;                  // 0..3
    const __half2* vb = g_vh + (size_t)(b * T_ + ch * 128) * (ENC_ / 2);
    float acc[8];
    #pragma unroll
    for (int k = 0; k < 8; k++) acc[k] = 0.f;
    #pragma unroll 4
    for (int r = parity; r < 128; r += 4) {
        float wt = sw[r];
        uint4 raw = *(const uint4*)(vb + (size_t)r * (ENC_ / 2) + col8 * 4);
        const __half2* h = (const __half2*)&raw;
        #pragma unroll
        for (int k = 0; k < 4; k++) {
            float2 f = __half22float2(h[k]);
            acc[2 * k + 0] += wt * f.x;
            acc[2 * k + 1] += wt * f.y;
        }
    }
    if (parity > 0) {
        #pragma unroll
        for (int k = 0; k < 8; k++) sh[parity - 1][col8][k] = acc[k];
    }
    __syncthreads();
    if (parity == 0) {
        #pragma unroll
        for (int k = 0; k < 8; k++)
            acc[k] += sh[0][col8][k] + sh[1][col8][k] + sh[2][col8][k];
        float4* dst = (float4*)&g_ctx_part[(size_t)(b * 16 + ch) * ENC_ + col8 * 8];
        dst[0] = make_float4(acc[0], acc[1], acc[2], acc[3]);
        dst[1] = make_float4(acc[4], acc[5], acc[6], acc[7]);
    }
}

__global__ void ctx_reduce(float* __restrict__ out_ctx) {
    int idx = blockIdx.x * 256 + threadIdx.x;
    int b = idx >> 9, c = idx & 511;
    float s = 0.f;
    #pragma unroll
    for (int ch = 0; ch < 16; ch++)
        s += g_ctx_part[(size_t)(b * 16 + ch) * ENC_ + c];
    out_ctx[idx] = s;
}

// ---------------------------------------------------------------------------
extern "C" void kernel_launch(void* const* d_in, const int* in_sizes, int n_in,
                              void* d_out, int out_size) {
    const float* query = (const float*)d_in[0];
    const float* values = (const float*)d_in[1];
    const float* caw   = (const float*)d_in[2];
    const unsigned char* mask = (const unsigned char*)d_in[3];
    const float* Qw    = (const float*)d_in[4];
    const float* Qb    = (const float*)d_in[5];
    const float* Vw    = (const float*)d_in[6];
    const float* convw = (const float*)d_in[7];
    const float* locp  = (const float*)d_in[8];
    const float* vw    = (const float*)d_in[9];

    float* out_ctx = (float*)d_out;              // [B, ENC]
    float* out_w   = (float*)d_out + B_ * ENC_;  // [B, T]

    cudaFuncSetAttribute(main_mma,
                         cudaFuncAttributeMaxDynamicSharedMemorySize, SMEM_MAIN);

    prep_kernel<<<200 + CVT_BLKS, 256>>>(query, Qw, Qb, Vw, locp, convw, values);
    main_mma<<<dim3(T_ / 128, B_), NT, SMEM_MAIN>>>(caw, vw);
    ctx_fused<<<dim3(16, B_), 256>>>(mask, out_w);
    ctx_reduce<<<(B_ * ENC_) / 256, 256>>>(out_ctx);
}